// round 9
// baseline (speedup 1.0000x reference)
#include <cuda_runtime.h>
#include <math.h>

#define BB   256     // batch
#define DM   512     // d_model
#define NV   1376    // n_vars
#define Gm   64      // batch rows per block
#define MAXS 128     // max slots supported (actual S = 96)

// ---------------- device-global scratch (no allocations allowed) ----------------
__device__ int g_S, g_total;
__device__ int g_c[MAXS], g_L[MAXS], g_k[MAXS], g_off[MAXS], g_ord[MAXS];
__device__ __align__(16) float g_pe[MAXS * DM];

// ---------------- setup: block 0 = plan, blocks 1..MAXS = positional emb -------
__global__ void setup_kernel(const int* __restrict__ seg) {
    if (blockIdx.x == 0) {
        __shared__ int sc[MAXS], sL[MAXS], sk[MAXS], sPl[MAXS], soff[MAXS];
        __shared__ int sFirstNeg, sS;
        int tid = threadIdx.x;
        if (tid == 0) { sFirstNeg = NV; sS = 0; }
        __syncthreads();
        for (int t = tid; t < NV; t += blockDim.x)
            if (seg[t] < 0) atomicMin(&sFirstNeg, t);
        __syncthreads();
        int validN = sFirstNeg;
        for (int t = tid; t < validN; t += blockDim.x) {
            int v = seg[t];
            int prev = (t == 0) ? -2 : seg[t - 1];
            if (v != prev) sc[v] = t;
            atomicMax(&sS, v + 1);
        }
        __syncthreads();
        int S = sS;
        const int PL[4] = {5, 10, 17, 24};
        for (int s = tid; s < S; s += blockDim.x) {
            int cs = sc[s];
            int L = ((s + 1 < S) ? sc[s + 1] : validN) - cs;
            int bestk = 0, bd = abs(L - PL[0]);
#pragma unroll
            for (int k = 1; k < 4; k++) {
                int dd = abs(L - PL[k]);
                if (dd < bd) { bd = dd; bestk = k; }   // strict < keeps first on tie
            }
            sL[s] = L; sk[s] = bestk; sPl[s] = PL[bestk];
        }
        __syncthreads();
        if (tid == 0) {
            int acc = 0;
            for (int s = 0; s < S; s++) { soff[s] = acc; acc += sPl[s]; }
            g_total = acc;
            g_S = S;
            // heavy-first launch order: slots sorted by bucket (P) descending
            int idx = 0;
            for (int bk = 3; bk >= 0; bk--)
                for (int s = 0; s < S; s++)
                    if (sk[s] == bk) g_ord[idx++] = s;
        }
        __syncthreads();
        for (int s = tid; s < S; s += blockDim.x) {
            g_c[s] = sc[s]; g_L[s] = sL[s]; g_k[s] = sk[s]; g_off[s] = soff[s];
        }
    } else {
        int s = blockIdx.x - 1;
        int j = threadIdx.x;                       // 0..255
        float freq = expf(-(float)(2 * j) * (logf(10000.0f) / (float)DM));
        float sv, cv;
        sincosf((float)s * freq, &sv, &cv);
        g_pe[s * DM + 2 * j]     = sv;
        g_pe[s * DM + 2 * j + 1] = cv;
    }
}

// ---------------- main embedding -----------------------------------------------
// One block = (slot s, 64 batch rows, all 512 channels). Per-bucket channel
// blocking: CH=4 (P=5,10): 128 d-threads x 2 g-halves, STG.128; CH=2 (P=17,24):
// 256 d-threads, full g range, STG.64. Thread's CH channel rows of W are
// CONTIGUOUS in gmem -> vectorized LDG straight to registers (no smem staging).
// Patch values staged in shared; inner loop = broadcast LDS.128 + fma.rn.f32x2,
// one accumulator chain per channel.
template <int P, int CH>
__device__ __forceinline__ void run_patch(
    const float* __restrict__ x, const float* __restrict__ Wk,
    float* __restrict__ out, float* __restrict__ mask_out, float (*sv)[32],
    int s, int b0, int c, int L, int S, int off, int total, int with_mask)
{
    constexpr int PP4 = (P + 3) & ~3;   // pad to multiple of 4 (zero slots)
    constexpr int NP2 = PP4 / 2;        // f32x2 pairs along t
    constexpr int NQ  = PP4 / 4;        // 16B quads along t
    int tid = threadIdx.x;

    // ---- stage patch values (zero padded) for Gm batch rows ----
#pragma unroll
    for (int i = tid; i < Gm * PP4; i += 256) {
        int g = i / PP4, t = i - g * PP4;
        float val = 0.0f;
        if (t < P && t < L) val = x[(size_t)(b0 + g) * NV + c + t];
        sv[g][t] = val;
    }

    // ---- thread's slice of channels / g range ----
    int dt, g0, ng;
    if (CH == 4) { dt = tid & 127; g0 = (tid >> 7) * 32; ng = 32; }
    else         { dt = tid;       g0 = 0;               ng = Gm; }
    int d0 = dt * CH;

    // ---- W rows for this thread's CH channels: CH*P contiguous floats ----
    float wf[CH * PP4];
    {
        const float* base = Wk + (size_t)d0 * P;
        if constexpr ((CH * P) % 4 == 0) {
            const float4* wg = reinterpret_cast<const float4*>(base);
#pragma unroll
            for (int i = 0; i < CH * P / 4; i++) {
                float4 v = wg[i];
                {int f=4*i+0; wf[(f/P)*PP4 + (f%P)] = v.x;}
                {int f=4*i+1; wf[(f/P)*PP4 + (f%P)] = v.y;}
                {int f=4*i+2; wf[(f/P)*PP4 + (f%P)] = v.z;}
                {int f=4*i+3; wf[(f/P)*PP4 + (f%P)] = v.w;}
            }
        } else {
            const float2* wg = reinterpret_cast<const float2*>(base);
#pragma unroll
            for (int i = 0; i < CH * P / 2; i++) {
                float2 v = wg[i];
                {int f=2*i+0; wf[(f/P)*PP4 + (f%P)] = v.x;}
                {int f=2*i+1; wf[(f/P)*PP4 + (f%P)] = v.y;}
            }
        }
#pragma unroll
        for (int ch = 0; ch < CH; ch++)
#pragma unroll
            for (int t = P; t < PP4; t++) wf[ch * PP4 + t] = 0.0f;
    }

    unsigned long long wp[CH][NP2];
#pragma unroll
    for (int ch = 0; ch < CH; ch++)
#pragma unroll
        for (int j = 0; j < NP2; j++)
            asm("mov.b64 %0, {%1, %2};" : "=l"(wp[ch][j])
                : "f"(wf[ch * PP4 + 2 * j]), "f"(wf[ch * PP4 + 2 * j + 1]));

    float pe_[CH];
#pragma unroll
    for (int ch = 0; ch < CH; ch++) pe_[ch] = g_pe[s * DM + d0 + ch];

    __syncthreads();

    float* op = out + ((size_t)(b0 + g0) * S + s) * DM + d0;
    const size_t ostride = (size_t)S * DM;

#pragma unroll 4
    for (int g = 0; g < ng; g++) {
        unsigned long long a[CH];
#pragma unroll
        for (int ch = 0; ch < CH; ch++) a[ch] = 0ull;
#pragma unroll
        for (int q = 0; q < NQ; q++) {
            ulonglong2 v = *reinterpret_cast<const ulonglong2*>(&sv[g0 + g][4 * q]);
#pragma unroll
            for (int ch = 0; ch < CH; ch++) {
                asm("fma.rn.f32x2 %0, %1, %2, %0;" : "+l"(a[ch]) : "l"(v.x), "l"(wp[ch][2 * q]));
                asm("fma.rn.f32x2 %0, %1, %2, %0;" : "+l"(a[ch]) : "l"(v.y), "l"(wp[ch][2 * q + 1]));
            }
        }
        float r[CH];
#pragma unroll
        for (int ch = 0; ch < CH; ch++) {
            float lo, hi;
            asm("mov.b64 {%0, %1}, %2;" : "=f"(lo), "=f"(hi) : "l"(a[ch]));
            r[ch] = (lo + hi) + pe_[ch];
        }
        if (CH == 4) {
            float4 o; o.x = r[0]; o.y = r[1]; o.z = r[2]; o.w = r[3];
            *reinterpret_cast<float4*>(op + (size_t)g * ostride) = o;
        } else {
            float2 o; o.x = r[0]; o.y = r[1];
            *reinterpret_cast<float2*>(op + (size_t)g * ostride) = o;
        }
    }

    // ---- this block's slice of the padding mask (off the critical path) ----
    if (with_mask) {
#pragma unroll
        for (int i = tid; i < Gm * P; i += 256) {
            int g = i / P, t = i - g * P;
            mask_out[(size_t)(b0 + g) * total + off + t] = (t >= L) ? 1.0f : 0.0f;
        }
    }
}

__global__ void __launch_bounds__(256, 3) embed_kernel(
    const float* __restrict__ x,
    const float* __restrict__ W0, const float* __restrict__ W1,
    const float* __restrict__ W2, const float* __restrict__ W3,
    float* __restrict__ out, int with_mask)
{
    __shared__ __align__(16) float sv[Gm][32];
    int j = blockIdx.y;
    int S = g_S;
    if (j >= S) return;
    int s = g_ord[j];                              // heavy-first ordering
    int total = g_total;
    float* mask_out = out + (size_t)BB * S * DM;
    int b0 = blockIdx.x * Gm;
    int c = g_c[s], L = g_L[s], k = g_k[s], off = g_off[s];
    switch (k) {
        case 0:  run_patch<5,  4>(x, W0, out, mask_out, sv, s, b0, c, L, S, off, total, with_mask); break;
        case 1:  run_patch<10, 4>(x, W1, out, mask_out, sv, s, b0, c, L, S, off, total, with_mask); break;
        case 2:  run_patch<17, 2>(x, W2, out, mask_out, sv, s, b0, c, L, S, off, total, with_mask); break;
        default: run_patch<24, 2>(x, W3, out, mask_out, sv, s, b0, c, L, S, off, total, with_mask); break;
    }
}

// ---------------- launch --------------------------------------------------------
extern "C" void kernel_launch(void* const* d_in, const int* in_sizes, int n_in,
                              void* d_out, int out_size) {
    const float* x   = (const float*)d_in[0];
    const int*   seg = (const int*)  d_in[1];
    const float* W0  = (const float*)d_in[2];
    const float* W1  = (const float*)d_in[3];
    const float* W2  = (const float*)d_in[4];
    const float* W3  = (const float*)d_in[5];
    float* out = (float*)d_out;

    // If the harness concatenates (out, mask) the total is not a multiple of B*D.
    int with_mask = (out_size % (BB * DM)) != 0;

    setup_kernel<<<MAXS + 1, 256>>>(seg);
    dim3 grid(BB / Gm, MAXS);   // 4 x 128 (96 active slots -> 384 work blocks)
    embed_kernel<<<grid, 256>>>(x, W0, W1, W2, W3, out, with_mask);
    (void)in_sizes; (void)n_in;
}

// round 10
// speedup vs baseline: 1.2436x; 1.2436x over previous
#include <cuda_runtime.h>
#include <math.h>

#define BB   256     // batch
#define DM   512     // d_model
#define NV   1376    // n_vars
#define Gm   64      // batch rows per block
#define MAXS 128     // max slots supported (actual S = 96)

// ---------------- device-global scratch (no allocations allowed) ----------------
__device__ int g_S, g_total;
__device__ int g_c[MAXS], g_L[MAXS], g_k[MAXS], g_off[MAXS], g_ord[MAXS];
__device__ __align__(16) float g_pe[MAXS * DM];

// ---------------- setup: block 0 = plan, blocks 1..MAXS = positional emb -------
__global__ void setup_kernel(const int* __restrict__ seg) {
    if (blockIdx.x == 0) {
        __shared__ int sc[MAXS], sL[MAXS], sk[MAXS], sPl[MAXS];
        __shared__ int sFirstNeg, sS;
        int tid = threadIdx.x;
        if (tid == 0) { sFirstNeg = NV; sS = 0; }
        __syncthreads();
        for (int t = tid; t < NV; t += blockDim.x)
            if (seg[t] < 0) atomicMin(&sFirstNeg, t);
        __syncthreads();
        int validN = sFirstNeg;
        for (int t = tid; t < validN; t += blockDim.x) {
            int v = seg[t];
            int prev = (t == 0) ? -2 : seg[t - 1];
            if (v != prev) sc[v] = t;
            atomicMax(&sS, v + 1);
        }
        __syncthreads();
        int S = sS;
        const int PL[4] = {5, 10, 17, 24};
        for (int s = tid; s < S; s += blockDim.x) {
            int cs = sc[s];
            int L = ((s + 1 < S) ? sc[s + 1] : validN) - cs;
            int bestk = 0, bd = abs(L - PL[0]);
#pragma unroll
            for (int k = 1; k < 4; k++) {
                int dd = abs(L - PL[k]);
                if (dd < bd) { bd = dd; bestk = k; }   // strict < keeps first on tie
            }
            sL[s] = L; sk[s] = bestk; sPl[s] = PL[bestk];
        }
        __syncthreads();
        // PARALLEL prefix sums + heavy-first rank (no serial tid==0 loops)
        for (int s = tid; s < S; s += blockDim.x) {
            int acc = 0;
            for (int j = 0; j < s; j++) acc += sPl[j];     // S<=128, shared reads
            g_off[s] = acc;
            if (s == S - 1) { g_total = acc + sPl[s]; g_S = S; }
            int bk = sk[s], r = 0;
            for (int j = 0; j < S; j++) {
                int bj = sk[j];
                if (bj > bk || (bj == bk && j < s)) r++;   // bucket desc, index asc
            }
            g_ord[r] = s;
            g_c[s] = sc[s]; g_L[s] = sL[s]; g_k[s] = bk;
        }
    } else {
        int s = blockIdx.x - 1;
        int j = threadIdx.x;                       // 0..255
        float freq = expf(-(float)(2 * j) * (logf(10000.0f) / (float)DM));
        float sv, cv;
        sincosf((float)s * freq, &sv, &cv);
        float2 o; o.x = sv; o.y = cv;
        *reinterpret_cast<float2*>(g_pe + s * DM + 2 * j) = o;
    }
}

// ---------------- main embedding -----------------------------------------------
// One block = (slot s, 64 batch rows, all 512 channels). Per-bucket channel
// blocking: CH=4 (P=5,10): 128 d-threads x 2 g-halves, STG.128; CH=2 (P=17,24):
// 256 d-threads, full g range, STG.64. Thread's CH channel rows of W are
// CONTIGUOUS in gmem -> vectorized LDG straight to registers (no smem staging).
// Patch values staged in shared; inner loop = broadcast LDS.128 + fma.rn.f32x2,
// one accumulator chain per channel.
template <int P, int CH>
__device__ __forceinline__ void run_patch(
    const float* __restrict__ x, const float* __restrict__ Wk,
    float* __restrict__ out, float* __restrict__ mask_out, float (*sv)[32],
    int s, int b0, int c, int L, int S, int off, int total, int with_mask)
{
    constexpr int PP4 = (P + 3) & ~3;   // pad to multiple of 4 (zero slots)
    constexpr int NP2 = PP4 / 2;        // f32x2 pairs along t
    constexpr int NQ  = PP4 / 4;        // 16B quads along t
    int tid = threadIdx.x;

    // ---- stage patch values (zero padded) for Gm batch rows ----
#pragma unroll
    for (int i = tid; i < Gm * PP4; i += 256) {
        int g = i / PP4, t = i - g * PP4;
        float val = 0.0f;
        if (t < P && t < L) val = x[(size_t)(b0 + g) * NV + c + t];
        sv[g][t] = val;
    }

    // ---- thread's slice of channels / g range ----
    int dt, g0, ng;
    if (CH == 4) { dt = tid & 127; g0 = (tid >> 7) * 32; ng = 32; }
    else         { dt = tid;       g0 = 0;               ng = Gm; }
    int d0 = dt * CH;

    // ---- W rows for this thread's CH channels: CH*P contiguous floats ----
    float wf[CH * PP4];
    {
        const float* base = Wk + (size_t)d0 * P;
        if constexpr ((CH * P) % 4 == 0) {
            const float4* wg = reinterpret_cast<const float4*>(base);
#pragma unroll
            for (int i = 0; i < CH * P / 4; i++) {
                float4 v = wg[i];
                {int f=4*i+0; wf[(f/P)*PP4 + (f%P)] = v.x;}
                {int f=4*i+1; wf[(f/P)*PP4 + (f%P)] = v.y;}
                {int f=4*i+2; wf[(f/P)*PP4 + (f%P)] = v.z;}
                {int f=4*i+3; wf[(f/P)*PP4 + (f%P)] = v.w;}
            }
        } else {
            const float2* wg = reinterpret_cast<const float2*>(base);
#pragma unroll
            for (int i = 0; i < CH * P / 2; i++) {
                float2 v = wg[i];
                {int f=2*i+0; wf[(f/P)*PP4 + (f%P)] = v.x;}
                {int f=2*i+1; wf[(f/P)*PP4 + (f%P)] = v.y;}
            }
        }
#pragma unroll
        for (int ch = 0; ch < CH; ch++)
#pragma unroll
            for (int t = P; t < PP4; t++) wf[ch * PP4 + t] = 0.0f;
    }

    unsigned long long wp[CH][NP2];
#pragma unroll
    for (int ch = 0; ch < CH; ch++)
#pragma unroll
        for (int j = 0; j < NP2; j++)
            asm("mov.b64 %0, {%1, %2};" : "=l"(wp[ch][j])
                : "f"(wf[ch * PP4 + 2 * j]), "f"(wf[ch * PP4 + 2 * j + 1]));

    float pe_[CH];
#pragma unroll
    for (int ch = 0; ch < CH; ch++) pe_[ch] = g_pe[s * DM + d0 + ch];

    __syncthreads();

    float* op = out + ((size_t)(b0 + g0) * S + s) * DM + d0;
    const size_t ostride = (size_t)S * DM;

#pragma unroll 4
    for (int g = 0; g < ng; g++) {
        unsigned long long a[CH];
#pragma unroll
        for (int ch = 0; ch < CH; ch++) a[ch] = 0ull;
#pragma unroll
        for (int q = 0; q < NQ; q++) {
            ulonglong2 v = *reinterpret_cast<const ulonglong2*>(&sv[g0 + g][4 * q]);
#pragma unroll
            for (int ch = 0; ch < CH; ch++) {
                asm("fma.rn.f32x2 %0, %1, %2, %0;" : "+l"(a[ch]) : "l"(v.x), "l"(wp[ch][2 * q]));
                asm("fma.rn.f32x2 %0, %1, %2, %0;" : "+l"(a[ch]) : "l"(v.y), "l"(wp[ch][2 * q + 1]));
            }
        }
        float r[CH];
#pragma unroll
        for (int ch = 0; ch < CH; ch++) {
            float lo, hi;
            asm("mov.b64 {%0, %1}, %2;" : "=f"(lo), "=f"(hi) : "l"(a[ch]));
            r[ch] = (lo + hi) + pe_[ch];
        }
        if (CH == 4) {
            float4 o; o.x = r[0]; o.y = r[1]; o.z = r[2]; o.w = r[3];
            *reinterpret_cast<float4*>(op + (size_t)g * ostride) = o;
        } else {
            float2 o; o.x = r[0]; o.y = r[1];
            *reinterpret_cast<float2*>(op + (size_t)g * ostride) = o;
        }
    }

    // ---- this block's slice of the padding mask (off the critical path) ----
    if (with_mask) {
#pragma unroll
        for (int i = tid; i < Gm * P; i += 256) {
            int g = i / P, t = i - g * P;
            mask_out[(size_t)(b0 + g) * total + off + t] = (t >= L) ? 1.0f : 0.0f;
        }
    }
}

__global__ void __launch_bounds__(256, 3) embed_kernel(
    const float* __restrict__ x,
    const float* __restrict__ W0, const float* __restrict__ W1,
    const float* __restrict__ W2, const float* __restrict__ W3,
    float* __restrict__ out, int with_mask)
{
    __shared__ __align__(16) float sv[Gm][32];
    int j = blockIdx.y;
    int S = g_S;
    if (j >= S) return;
    int s = g_ord[j];                              // heavy-first ordering
    int total = g_total;
    float* mask_out = out + (size_t)BB * S * DM;
    int b0 = blockIdx.x * Gm;
    int c = g_c[s], L = g_L[s], k = g_k[s], off = g_off[s];
    switch (k) {
        case 0:  run_patch<5,  4>(x, W0, out, mask_out, sv, s, b0, c, L, S, off, total, with_mask); break;
        case 1:  run_patch<10, 4>(x, W1, out, mask_out, sv, s, b0, c, L, S, off, total, with_mask); break;
        case 2:  run_patch<17, 2>(x, W2, out, mask_out, sv, s, b0, c, L, S, off, total, with_mask); break;
        default: run_patch<24, 2>(x, W3, out, mask_out, sv, s, b0, c, L, S, off, total, with_mask); break;
    }
}

// ---------------- launch --------------------------------------------------------
extern "C" void kernel_launch(void* const* d_in, const int* in_sizes, int n_in,
                              void* d_out, int out_size) {
    const float* x   = (const float*)d_in[0];
    const int*   seg = (const int*)  d_in[1];
    const float* W0  = (const float*)d_in[2];
    const float* W1  = (const float*)d_in[3];
    const float* W2  = (const float*)d_in[4];
    const float* W3  = (const float*)d_in[5];
    float* out = (float*)d_out;

    // If the harness concatenates (out, mask) the total is not a multiple of B*D.
    int with_mask = (out_size % (BB * DM)) != 0;

    setup_kernel<<<MAXS + 1, 256>>>(seg);
    dim3 grid(BB / Gm, MAXS);   // 4 x 128 (96 active slots -> 384 work blocks)
    embed_kernel<<<grid, 256>>>(x, W0, W1, W2, W3, out, with_mask);
    (void)in_sizes; (void)n_in;
}